// round 7
// baseline (speedup 1.0000x reference)
#include <cuda_runtime.h>

#define N_VUL 100000
#define N_SRC 50000
#define N_EDGE 500000
#define D 128
#define NREL 3
#define CAP 32    // max in-degree per (rel,dst). Poisson(5): P(>32) ~ 1e-18.

// Static scratch (allocation is forbidden).
// Self-cleaning invariant: g_cnt is all-zero at entry to every kernel_launch
// (zero-initialized at module load; pull_kernel re-zeroes after reading).
__device__ int g_cnt[NREL][N_VUL];            // per-(rel,dst) cursor == in-degree
__device__ int g_bucket[NREL][N_VUL][CAP];    // src ids per (rel,dst), 38.4 MB

// Bucketize all three relations in one pass over the edge lists.
__global__ void fill_kernel(const int* __restrict__ sa, const int* __restrict__ da,
                            const int* __restrict__ sb, const int* __restrict__ db,
                            const int* __restrict__ sc, const int* __restrict__ dc) {
    const int tid    = blockIdx.x * blockDim.x + threadIdx.x;
    const int stride = gridDim.x * blockDim.x;
    for (int e = tid; e < N_EDGE; e += stride) {
        int d, p;
        d = da[e]; p = atomicAdd(&g_cnt[0][d], 1); if (p < CAP) g_bucket[0][d][p] = sa[e];
        d = db[e]; p = atomicAdd(&g_cnt[1][d], 1); if (p < CAP) g_bucket[1][d][p] = sb[e];
        d = dc[e]; p = atomicAdd(&g_cnt[2][d], 1); if (p < CAP) g_bucket[2][d][p] = sc[e];
    }
}

// One warp per destination row. Lane l owns float4 l of the 128-float row.
// Per relation: one strided entry load per 32 edges, shfl broadcast, unroll-4
// inner loop (proven fastest shape: 18 regs, occ ~78%, MLP ~4).
// Computes recip inline and self-cleans the counters.
__global__ void pull_kernel(const float4* __restrict__ xa,
                            const float4* __restrict__ xb,
                            const float4* __restrict__ xc,
                            float4* __restrict__ out) {
    const int gtid = blockIdx.x * blockDim.x + threadIdx.x;
    const int dst  = gtid >> 5;
    const int lane = gtid & 31;
    if (dst >= N_VUL) return;

    float4 acc = make_float4(0.f, 0.f, 0.f, 0.f);

    const float4* __restrict__ xs[NREL] = { xa, xb, xc };
#pragma unroll
    for (int r = 0; r < NREL; r++) {
        const int c_full = g_cnt[r][dst];
        const int c      = c_full < CAP ? c_full : CAP;
        if (lane == 0) g_cnt[r][dst] = 0;      // self-clean for next invocation

        float4 a = make_float4(0.f, 0.f, 0.f, 0.f);
        const float4* __restrict__ x = xs[r];
        const int* __restrict__ bkt = g_bucket[r][dst];

        // c <= 32: single strided entry load + shfl-broadcast inner loop.
        int myidx = (lane < c) ? bkt[lane] : 0;
#pragma unroll 4
        for (int e = 0; e < c; e++) {
            const int s = __shfl_sync(0xFFFFFFFFu, myidx, e);
            const float4 v = x[s * (D / 4) + lane];
            a.x += v.x; a.y += v.y; a.z += v.z; a.w += v.w;
        }

        const float recip = 1.0f / (3.0f * (float)(c_full > 0 ? c_full : 1));
        acc.x = fmaf(a.x, recip, acc.x);
        acc.y = fmaf(a.y, recip, acc.y);
        acc.z = fmaf(a.z, recip, acc.z);
        acc.w = fmaf(a.w, recip, acc.w);
    }

    out[dst * (D / 4) + lane] = acc;
}

extern "C" void kernel_launch(void* const* d_in, const int* in_sizes, int n_in,
                              void* d_out, int out_size) {
    // metadata order: x_a, x_b, x_c, src_a, dst_a, src_b, dst_b, src_c, dst_c
    const float* xa = (const float*)d_in[0];
    const float* xb = (const float*)d_in[1];
    const float* xc = (const float*)d_in[2];
    const int* sa = (const int*)d_in[3];
    const int* da = (const int*)d_in[4];
    const int* sb = (const int*)d_in[5];
    const int* db = (const int*)d_in[6];
    const int* sc = (const int*)d_in[7];
    const int* dc = (const int*)d_in[8];
    float* out = (float*)d_out;

    fill_kernel<<<1954, 256>>>(sa, da, sb, db, sc, dc);   // ~1 edge/thread/rel

    // 100000 dsts * 32 threads; 8 warps/block -> 12500 blocks
    pull_kernel<<<12500, 256>>>((const float4*)xa, (const float4*)xb,
                                (const float4*)xc, (float4*)out);
}

// round 8
// speedup vs baseline: 2.7396x; 2.7396x over previous
#include <cuda_runtime.h>

#define N_VUL 100000
#define N_SRC 50000
#define N_EDGE 500000
#define D 128
#define NREL 3
#define CAP 64            // max in-degree per (rel,dst). Poisson(5): P(>32)~1e-18.

// Static scratch (allocation is forbidden).
__device__ int g_cur[NREL][N_VUL];              // per-(rel,dst) cursor == in-degree
__device__ int g_bucket[NREL][N_VUL][CAP];      // src ids per (rel,dst)  (76.8 MB)

__global__ void zero_cursors() {
    const int tid    = blockIdx.x * blockDim.x + threadIdx.x;
    const int stride = gridDim.x * blockDim.x;
    int* cur = &g_cur[0][0];
    for (int i = tid; i < NREL * N_VUL; i += stride) cur[i] = 0;
}

// Bucketize all three relations in one pass over the edge lists.
__global__ void fill_kernel(const int* __restrict__ sa, const int* __restrict__ da,
                            const int* __restrict__ sb, const int* __restrict__ db,
                            const int* __restrict__ sc, const int* __restrict__ dc) {
    const int tid    = blockIdx.x * blockDim.x + threadIdx.x;
    const int stride = gridDim.x * blockDim.x;
    for (int e = tid; e < N_EDGE; e += stride) {
        int d, p;
        d = da[e]; p = atomicAdd(&g_cur[0][d], 1); if (p < CAP) g_bucket[0][d][p] = sa[e];
        d = db[e]; p = atomicAdd(&g_cur[1][d], 1); if (p < CAP) g_bucket[1][d][p] = sb[e];
        d = dc[e]; p = atomicAdd(&g_cur[2][d], 1); if (p < CAP) g_bucket[2][d][p] = sc[e];
    }
}

// One warp per destination row. Lane l owns float4 l of the 128-float row.
// Per relation: sum the gathered source rows, scale by 1/(3*max(cnt,1)),
// accumulate across relations, write each output float4 exactly once.
__global__ void pull_kernel(const float4* __restrict__ xa,
                            const float4* __restrict__ xb,
                            const float4* __restrict__ xc,
                            float4* __restrict__ out) {
    const int gtid = blockIdx.x * blockDim.x + threadIdx.x;
    const int dst  = gtid >> 5;
    const int lane = gtid & 31;
    if (dst >= N_VUL) return;

    float4 acc = make_float4(0.f, 0.f, 0.f, 0.f);

    const float4* __restrict__ xs[NREL] = { xa, xb, xc };
#pragma unroll
    for (int r = 0; r < NREL; r++) {
        const int c_full = g_cur[r][dst];
        const int c      = c_full < CAP ? c_full : CAP;
        float4 a = make_float4(0.f, 0.f, 0.f, 0.f);
        const float4* __restrict__ x = xs[r];
        const int* __restrict__ bkt = g_bucket[r][dst];

        for (int base = 0; base < c; base += 32) {
            const int n = (c - base) < 32 ? (c - base) : 32;
            // each lane fetches one edge's src id, then broadcast via shfl
            int myidx = (base + lane < c) ? bkt[base + lane] : 0;
#pragma unroll 8
            for (int e = 0; e < n; e++) {
                const int s = __shfl_sync(0xFFFFFFFFu, myidx, e);
                const float4 v = x[s * (D / 4) + lane];
                a.x += v.x; a.y += v.y; a.z += v.z; a.w += v.w;
            }
        }
        const float recip = 1.0f / (3.0f * (float)(c_full > 0 ? c_full : 1));
        acc.x += a.x * recip; acc.y += a.y * recip;
        acc.z += a.z * recip; acc.w += a.w * recip;
    }

    out[dst * (D / 4) + lane] = acc;
}

extern "C" void kernel_launch(void* const* d_in, const int* in_sizes, int n_in,
                              void* d_out, int out_size) {
    // metadata order: x_a, x_b, x_c, src_a, dst_a, src_b, dst_b, src_c, dst_c
    const float* xa = (const float*)d_in[0];
    const float* xb = (const float*)d_in[1];
    const float* xc = (const float*)d_in[2];
    const int* sa = (const int*)d_in[3];
    const int* da = (const int*)d_in[4];
    const int* sb = (const int*)d_in[5];
    const int* db = (const int*)d_in[6];
    const int* sc = (const int*)d_in[7];
    const int* dc = (const int*)d_in[8];
    float* out = (float*)d_out;

    zero_cursors<<<296, 256>>>();
    fill_kernel<<<977, 256>>>(sa, da, sb, db, sc, dc);   // ~2 edges/thread

    // 100000 dsts * 32 threads = 3.2M threads; 8 warps/block -> 12500 blocks
    pull_kernel<<<12500, 256>>>((const float4*)xa, (const float4*)xb,
                                (const float4*)xc, (float4*)out);
}

// round 9
// speedup vs baseline: 3.5026x; 1.2785x over previous
#include <cuda_runtime.h>

#define N_VUL 100000
#define N_SRC 50000
#define N_EDGE 500000
#define D 128
#define NREL 3
#define CAP 64            // max in-degree per (rel,dst). Poisson(5): P(>32)~1e-18.

// Static scratch (allocation is forbidden).
__device__ int g_cur[NREL][N_VUL];              // per-(rel,dst) cursor == in-degree
__device__ int g_bucket[NREL][N_VUL][CAP];      // src ids per (rel,dst)  (76.8 MB)

__global__ void zero_cursors() {
    const int tid    = blockIdx.x * blockDim.x + threadIdx.x;
    const int stride = gridDim.x * blockDim.x;
    int* cur = &g_cur[0][0];
    for (int i = tid; i < NREL * N_VUL; i += stride) cur[i] = 0;
}

// Bucketize all three relations in one pass over the edge lists.
__global__ void fill_kernel(const int* __restrict__ sa, const int* __restrict__ da,
                            const int* __restrict__ sb, const int* __restrict__ db,
                            const int* __restrict__ sc, const int* __restrict__ dc) {
    const int tid    = blockIdx.x * blockDim.x + threadIdx.x;
    const int stride = gridDim.x * blockDim.x;
    for (int e = tid; e < N_EDGE; e += stride) {
        int d, p;
        d = da[e]; p = atomicAdd(&g_cur[0][d], 1); if (p < CAP) g_bucket[0][d][p] = sa[e];
        d = db[e]; p = atomicAdd(&g_cur[1][d], 1); if (p < CAP) g_bucket[1][d][p] = sb[e];
        d = dc[e]; p = atomicAdd(&g_cur[2][d], 1); if (p < CAP) g_bucket[2][d][p] = sc[e];
    }
}

// Sum up to n (<=32) gathered rows whose src ids sit in myidx across lanes.
// Identical body to the proven R4 inner loop: shfl broadcast + unroll 4.
__device__ __forceinline__ float4 batch_sum(const float4* __restrict__ x,
                                            int myidx, int n, int lane, float4 a) {
#pragma unroll 4
    for (int e = 0; e < n; e++) {
        const int s = __shfl_sync(0xFFFFFFFFu, myidx, e);
        const float4 v = x[s * (D / 4) + lane];
        a.x += v.x; a.y += v.y; a.z += v.z; a.w += v.w;
    }
    return a;
}

// One warp per destination row. Lane l owns float4 l of the 128-float row.
// All 3 count loads + all 3 first-batch entry loads hoisted to the top so the
// metadata latency of the three relations overlaps instead of serializing.
__global__ void pull_kernel(const float4* __restrict__ xa,
                            const float4* __restrict__ xb,
                            const float4* __restrict__ xc,
                            float4* __restrict__ out) {
    const int gtid = blockIdx.x * blockDim.x + threadIdx.x;
    const int dst  = gtid >> 5;
    const int lane = gtid & 31;
    if (dst >= N_VUL) return;

    // 3 independent count loads.
    const int cf0 = g_cur[0][dst];
    const int cf1 = g_cur[1][dst];
    const int cf2 = g_cur[2][dst];
    const int c0 = cf0 < CAP ? cf0 : CAP;
    const int c1 = cf1 < CAP ? cf1 : CAP;
    const int c2 = cf2 < CAP ? cf2 : CAP;

    const int* __restrict__ b0 = g_bucket[0][dst];
    const int* __restrict__ b1 = g_bucket[1][dst];
    const int* __restrict__ b2 = g_bucket[2][dst];

    // 3 independent first-batch entry loads.
    const int my0 = (lane < c0) ? b0[lane] : 0;
    const int my1 = (lane < c1) ? b1[lane] : 0;
    const int my2 = (lane < c2) ? b2[lane] : 0;

    float4 acc = make_float4(0.f, 0.f, 0.f, 0.f);

    // relation 0
    {
        float4 a = make_float4(0.f, 0.f, 0.f, 0.f);
        a = batch_sum(xa, my0, c0 < 32 ? c0 : 32, lane, a);
        for (int base = 32; base < c0; base += 32) {          // cold path
            int mi = (base + lane < c0) ? b0[base + lane] : 0;
            a = batch_sum(xa, mi, (c0 - base) < 32 ? (c0 - base) : 32, lane, a);
        }
        const float recip = 1.0f / (3.0f * (float)(cf0 > 0 ? cf0 : 1));
        acc.x += a.x * recip; acc.y += a.y * recip;
        acc.z += a.z * recip; acc.w += a.w * recip;
    }
    // relation 1
    {
        float4 a = make_float4(0.f, 0.f, 0.f, 0.f);
        a = batch_sum(xb, my1, c1 < 32 ? c1 : 32, lane, a);
        for (int base = 32; base < c1; base += 32) {          // cold path
            int mi = (base + lane < c1) ? b1[base + lane] : 0;
            a = batch_sum(xb, mi, (c1 - base) < 32 ? (c1 - base) : 32, lane, a);
        }
        const float recip = 1.0f / (3.0f * (float)(cf1 > 0 ? cf1 : 1));
        acc.x += a.x * recip; acc.y += a.y * recip;
        acc.z += a.z * recip; acc.w += a.w * recip;
    }
    // relation 2
    {
        float4 a = make_float4(0.f, 0.f, 0.f, 0.f);
        a = batch_sum(xc, my2, c2 < 32 ? c2 : 32, lane, a);
        for (int base = 32; base < c2; base += 32) {          // cold path
            int mi = (base + lane < c2) ? b2[base + lane] : 0;
            a = batch_sum(xc, mi, (c2 - base) < 32 ? (c2 - base) : 32, lane, a);
        }
        const float recip = 1.0f / (3.0f * (float)(cf2 > 0 ? cf2 : 1));
        acc.x += a.x * recip; acc.y += a.y * recip;
        acc.z += a.z * recip; acc.w += a.w * recip;
    }

    out[dst * (D / 4) + lane] = acc;
}

extern "C" void kernel_launch(void* const* d_in, const int* in_sizes, int n_in,
                              void* d_out, int out_size) {
    // metadata order: x_a, x_b, x_c, src_a, dst_a, src_b, dst_b, src_c, dst_c
    const float* xa = (const float*)d_in[0];
    const float* xb = (const float*)d_in[1];
    const float* xc = (const float*)d_in[2];
    const int* sa = (const int*)d_in[3];
    const int* da = (const int*)d_in[4];
    const int* sb = (const int*)d_in[5];
    const int* db = (const int*)d_in[6];
    const int* sc = (const int*)d_in[7];
    const int* dc = (const int*)d_in[8];
    float* out = (float*)d_out;

    zero_cursors<<<296, 256>>>();
    fill_kernel<<<977, 256>>>(sa, da, sb, db, sc, dc);   // ~2 edges/thread

    // 100000 dsts * 32 threads = 3.2M threads; 8 warps/block -> 12500 blocks
    pull_kernel<<<12500, 256>>>((const float4*)xa, (const float4*)xb,
                                (const float4*)xc, (float4*)out);
}

// round 10
// speedup vs baseline: 4.0389x; 1.1531x over previous
#include <cuda_runtime.h>
#include <cuda_fp16.h>

#define N_VUL 100000
#define N_SRC 50000
#define N_EDGE 500000
#define D 128
#define NREL 3
#define CAP 64            // max in-degree per (rel,dst). Poisson(5): P(>32)~1e-18.

// Static scratch (allocation is forbidden).
__device__ int g_cur[NREL][N_VUL];              // per-(rel,dst) cursor == in-degree
__device__ int g_bucket[NREL][N_VUL][CAP];      // src ids per (rel,dst)  (76.8 MB)
__device__ __half g_xh[NREL][N_SRC][D];         // fp16 mirror of x tables (38.4 MB)

__global__ void zero_cursors() {
    const int tid    = blockIdx.x * blockDim.x + threadIdx.x;
    const int stride = gridDim.x * blockDim.x;
    int* cur = &g_cur[0][0];
    for (int i = tid; i < NREL * N_VUL; i += stride) cur[i] = 0;
}

// Convert the three f32 feature tables to fp16 (fp32 accumulation keeps accuracy).
__global__ void convert_kernel(const float4* __restrict__ xa,
                               const float4* __restrict__ xb,
                               const float4* __restrict__ xc) {
    const int tid    = blockIdx.x * blockDim.x + threadIdx.x;
    const int stride = gridDim.x * blockDim.x;
    const int n4 = N_SRC * D / 4;                 // 1.6M float4 per table
    const float4* __restrict__ xs[NREL] = { xa, xb, xc };
#pragma unroll
    for (int r = 0; r < NREL; r++) {
        const float4* __restrict__ x = xs[r];
        uint2* __restrict__ dst = (uint2*)&g_xh[r][0][0];
        for (int i = tid; i < n4; i += stride) {
            const float4 v = x[i];
            __half2 h0 = __floats2half2_rn(v.x, v.y);
            __half2 h1 = __floats2half2_rn(v.z, v.w);
            uint2 packed;
            packed.x = *(const unsigned int*)&h0;
            packed.y = *(const unsigned int*)&h1;
            dst[i] = packed;
        }
    }
}

// Bucketize all three relations in one pass over the edge lists.
__global__ void fill_kernel(const int* __restrict__ sa, const int* __restrict__ da,
                            const int* __restrict__ sb, const int* __restrict__ db,
                            const int* __restrict__ sc, const int* __restrict__ dc) {
    const int tid    = blockIdx.x * blockDim.x + threadIdx.x;
    const int stride = gridDim.x * blockDim.x;
    for (int e = tid; e < N_EDGE; e += stride) {
        int d, p;
        d = da[e]; p = atomicAdd(&g_cur[0][d], 1); if (p < CAP) g_bucket[0][d][p] = sa[e];
        d = db[e]; p = atomicAdd(&g_cur[1][d], 1); if (p < CAP) g_bucket[1][d][p] = sb[e];
        d = dc[e]; p = atomicAdd(&g_cur[2][d], 1); if (p < CAP) g_bucket[2][d][p] = sc[e];
    }
}

// Sum up to n (<=32) gathered fp16 rows (fp32 accumulate). Proven R4/R9 inner
// loop shape: shfl broadcast + unroll 4; only the load width changed (8B).
__device__ __forceinline__ float4 batch_sum(const uint2* __restrict__ xh,
                                            int myidx, int n, int lane, float4 a) {
#pragma unroll 4
    for (int e = 0; e < n; e++) {
        const int s = __shfl_sync(0xFFFFFFFFu, myidx, e);
        const uint2 h = xh[s * (D / 4) + lane];       // 4 halves: cols 4*lane..+3
        const float2 f0 = __half22float2(*(const __half2*)&h.x);
        const float2 f1 = __half22float2(*(const __half2*)&h.y);
        a.x += f0.x; a.y += f0.y; a.z += f1.x; a.w += f1.y;
    }
    return a;
}

// One warp per destination row. Lane l owns float cols [4l, 4l+4).
// All 3 count loads + all 3 first-batch entry loads hoisted (R9 win).
__global__ void pull_kernel(float4* __restrict__ out) {
    const int gtid = blockIdx.x * blockDim.x + threadIdx.x;
    const int dst  = gtid >> 5;
    const int lane = gtid & 31;
    if (dst >= N_VUL) return;

    // 3 independent count loads.
    const int cf0 = g_cur[0][dst];
    const int cf1 = g_cur[1][dst];
    const int cf2 = g_cur[2][dst];
    const int c0 = cf0 < CAP ? cf0 : CAP;
    const int c1 = cf1 < CAP ? cf1 : CAP;
    const int c2 = cf2 < CAP ? cf2 : CAP;

    const int* __restrict__ b0 = g_bucket[0][dst];
    const int* __restrict__ b1 = g_bucket[1][dst];
    const int* __restrict__ b2 = g_bucket[2][dst];

    // 3 independent first-batch entry loads.
    const int my0 = (lane < c0) ? b0[lane] : 0;
    const int my1 = (lane < c1) ? b1[lane] : 0;
    const int my2 = (lane < c2) ? b2[lane] : 0;

    const uint2* __restrict__ xh0 = (const uint2*)&g_xh[0][0][0];
    const uint2* __restrict__ xh1 = (const uint2*)&g_xh[1][0][0];
    const uint2* __restrict__ xh2 = (const uint2*)&g_xh[2][0][0];

    float4 acc = make_float4(0.f, 0.f, 0.f, 0.f);

    // relation 0
    {
        float4 a = make_float4(0.f, 0.f, 0.f, 0.f);
        a = batch_sum(xh0, my0, c0 < 32 ? c0 : 32, lane, a);
        for (int base = 32; base < c0; base += 32) {          // cold path
            int mi = (base + lane < c0) ? b0[base + lane] : 0;
            a = batch_sum(xh0, mi, (c0 - base) < 32 ? (c0 - base) : 32, lane, a);
        }
        const float recip = 1.0f / (3.0f * (float)(cf0 > 0 ? cf0 : 1));
        acc.x += a.x * recip; acc.y += a.y * recip;
        acc.z += a.z * recip; acc.w += a.w * recip;
    }
    // relation 1
    {
        float4 a = make_float4(0.f, 0.f, 0.f, 0.f);
        a = batch_sum(xh1, my1, c1 < 32 ? c1 : 32, lane, a);
        for (int base = 32; base < c1; base += 32) {          // cold path
            int mi = (base + lane < c1) ? b1[base + lane] : 0;
            a = batch_sum(xh1, mi, (c1 - base) < 32 ? (c1 - base) : 32, lane, a);
        }
        const float recip = 1.0f / (3.0f * (float)(cf1 > 0 ? cf1 : 1));
        acc.x += a.x * recip; acc.y += a.y * recip;
        acc.z += a.z * recip; acc.w += a.w * recip;
    }
    // relation 2
    {
        float4 a = make_float4(0.f, 0.f, 0.f, 0.f);
        a = batch_sum(xh2, my2, c2 < 32 ? c2 : 32, lane, a);
        for (int base = 32; base < c2; base += 32) {          // cold path
            int mi = (base + lane < c2) ? b2[base + lane] : 0;
            a = batch_sum(xh2, mi, (c2 - base) < 32 ? (c2 - base) : 32, lane, a);
        }
        const float recip = 1.0f / (3.0f * (float)(cf2 > 0 ? cf2 : 1));
        acc.x += a.x * recip; acc.y += a.y * recip;
        acc.z += a.z * recip; acc.w += a.w * recip;
    }

    out[dst * (D / 4) + lane] = acc;
}

extern "C" void kernel_launch(void* const* d_in, const int* in_sizes, int n_in,
                              void* d_out, int out_size) {
    // metadata order: x_a, x_b, x_c, src_a, dst_a, src_b, dst_b, src_c, dst_c
    const float* xa = (const float*)d_in[0];
    const float* xb = (const float*)d_in[1];
    const float* xc = (const float*)d_in[2];
    const int* sa = (const int*)d_in[3];
    const int* da = (const int*)d_in[4];
    const int* sb = (const int*)d_in[5];
    const int* db = (const int*)d_in[6];
    const int* sc = (const int*)d_in[7];
    const int* dc = (const int*)d_in[8];
    float* out = (float*)d_out;

    zero_cursors<<<296, 256>>>();
    fill_kernel<<<977, 256>>>(sa, da, sb, db, sc, dc);   // ~2 edges/thread
    convert_kernel<<<2048, 256>>>((const float4*)xa, (const float4*)xb,
                                  (const float4*)xc);

    // 100000 dsts * 32 threads = 3.2M threads; 8 warps/block -> 12500 blocks
    pull_kernel<<<12500, 256>>>((float4*)out);
}

// round 11
// speedup vs baseline: 4.2127x; 1.0430x over previous
#include <cuda_runtime.h>
#include <cuda_fp16.h>

#define N_VUL 100000
#define N_SRC 50000
#define N_EDGE 500000
#define D 128
#define NREL 3
#define CAP 64            // max in-degree per (rel,dst). Poisson(5): P(>32)~1e-18.

#define FILL_BLOCKS 977
#define CONV_BLOCKS 2048

// Static scratch (allocation is forbidden).
__device__ int g_cur[NREL][N_VUL];              // per-(rel,dst) cursor == in-degree
__device__ int g_bucket[NREL][N_VUL][CAP];      // src ids per (rel,dst)  (76.8 MB)
__device__ __half g_xh[NREL][N_SRC][D];         // fp16 mirror of x tables (38.4 MB)

__global__ void zero_cursors() {
    const int tid    = blockIdx.x * blockDim.x + threadIdx.x;
    const int stride = gridDim.x * blockDim.x;
    int* cur = &g_cur[0][0];
    for (int i = tid; i < NREL * N_VUL; i += stride) cur[i] = 0;
}

// Fused kernel: blocks [0, FILL_BLOCKS) bucketize edges (atomic-latency-bound);
// blocks [FILL_BLOCKS, FILL_BLOCKS+CONV_BLOCKS) convert x tables to fp16
// (bandwidth-bound). Disjoint resources -> concurrent execution.
__global__ void fill_convert_kernel(const int* __restrict__ sa, const int* __restrict__ da,
                                    const int* __restrict__ sb, const int* __restrict__ db,
                                    const int* __restrict__ sc, const int* __restrict__ dc,
                                    const float4* __restrict__ xa,
                                    const float4* __restrict__ xb,
                                    const float4* __restrict__ xc) {
    if (blockIdx.x < FILL_BLOCKS) {
        const int tid    = blockIdx.x * blockDim.x + threadIdx.x;
        const int stride = FILL_BLOCKS * blockDim.x;
        for (int e = tid; e < N_EDGE; e += stride) {
            int d, p;
            d = da[e]; p = atomicAdd(&g_cur[0][d], 1); if (p < CAP) g_bucket[0][d][p] = sa[e];
            d = db[e]; p = atomicAdd(&g_cur[1][d], 1); if (p < CAP) g_bucket[1][d][p] = sb[e];
            d = dc[e]; p = atomicAdd(&g_cur[2][d], 1); if (p < CAP) g_bucket[2][d][p] = sc[e];
        }
    } else {
        const int tid    = (blockIdx.x - FILL_BLOCKS) * blockDim.x + threadIdx.x;
        const int stride = CONV_BLOCKS * blockDim.x;
        const int n4 = N_SRC * D / 4;                 // 1.6M float4 per table
        const float4* __restrict__ xs[NREL] = { xa, xb, xc };
#pragma unroll
        for (int r = 0; r < NREL; r++) {
            const float4* __restrict__ x = xs[r];
            uint2* __restrict__ dst = (uint2*)&g_xh[r][0][0];
            for (int i = tid; i < n4; i += stride) {
                const float4 v = x[i];
                __half2 h0 = __floats2half2_rn(v.x, v.y);
                __half2 h1 = __floats2half2_rn(v.z, v.w);
                uint2 packed;
                packed.x = *(const unsigned int*)&h0;
                packed.y = *(const unsigned int*)&h1;
                dst[i] = packed;
            }
        }
    }
}

// Sum up to n (<=32) gathered fp16 rows (fp32 accumulate). Proven R10 inner
// loop shape: shfl broadcast + unroll 4, 8B loads. DO NOT RESTRUCTURE.
__device__ __forceinline__ float4 batch_sum(const uint2* __restrict__ xh,
                                            int myidx, int n, int lane, float4 a) {
#pragma unroll 4
    for (int e = 0; e < n; e++) {
        const int s = __shfl_sync(0xFFFFFFFFu, myidx, e);
        const uint2 h = xh[s * (D / 4) + lane];       // 4 halves: cols 4*lane..+3
        const float2 f0 = __half22float2(*(const __half2*)&h.x);
        const float2 f1 = __half22float2(*(const __half2*)&h.y);
        a.x += f0.x; a.y += f0.y; a.z += f1.x; a.w += f1.y;
    }
    return a;
}

// One warp per destination row. Lane l owns float cols [4l, 4l+4).
// All 3 count loads + all 3 first-batch entry loads hoisted (R9 win).
// Byte-identical to the proven 62.4us R10 kernel.
__global__ void pull_kernel(float4* __restrict__ out) {
    const int gtid = blockIdx.x * blockDim.x + threadIdx.x;
    const int dst  = gtid >> 5;
    const int lane = gtid & 31;
    if (dst >= N_VUL) return;

    // 3 independent count loads.
    const int cf0 = g_cur[0][dst];
    const int cf1 = g_cur[1][dst];
    const int cf2 = g_cur[2][dst];
    const int c0 = cf0 < CAP ? cf0 : CAP;
    const int c1 = cf1 < CAP ? cf1 : CAP;
    const int c2 = cf2 < CAP ? cf2 : CAP;

    const int* __restrict__ b0 = g_bucket[0][dst];
    const int* __restrict__ b1 = g_bucket[1][dst];
    const int* __restrict__ b2 = g_bucket[2][dst];

    // 3 independent first-batch entry loads.
    const int my0 = (lane < c0) ? b0[lane] : 0;
    const int my1 = (lane < c1) ? b1[lane] : 0;
    const int my2 = (lane < c2) ? b2[lane] : 0;

    const uint2* __restrict__ xh0 = (const uint2*)&g_xh[0][0][0];
    const uint2* __restrict__ xh1 = (const uint2*)&g_xh[1][0][0];
    const uint2* __restrict__ xh2 = (const uint2*)&g_xh[2][0][0];

    float4 acc = make_float4(0.f, 0.f, 0.f, 0.f);

    // relation 0
    {
        float4 a = make_float4(0.f, 0.f, 0.f, 0.f);
        a = batch_sum(xh0, my0, c0 < 32 ? c0 : 32, lane, a);
        for (int base = 32; base < c0; base += 32) {          // cold path
            int mi = (base + lane < c0) ? b0[base + lane] : 0;
            a = batch_sum(xh0, mi, (c0 - base) < 32 ? (c0 - base) : 32, lane, a);
        }
        const float recip = 1.0f / (3.0f * (float)(cf0 > 0 ? cf0 : 1));
        acc.x += a.x * recip; acc.y += a.y * recip;
        acc.z += a.z * recip; acc.w += a.w * recip;
    }
    // relation 1
    {
        float4 a = make_float4(0.f, 0.f, 0.f, 0.f);
        a = batch_sum(xh1, my1, c1 < 32 ? c1 : 32, lane, a);
        for (int base = 32; base < c1; base += 32) {          // cold path
            int mi = (base + lane < c1) ? b1[base + lane] : 0;
            a = batch_sum(xh1, mi, (c1 - base) < 32 ? (c1 - base) : 32, lane, a);
        }
        const float recip = 1.0f / (3.0f * (float)(cf1 > 0 ? cf1 : 1));
        acc.x += a.x * recip; acc.y += a.y * recip;
        acc.z += a.z * recip; acc.w += a.w * recip;
    }
    // relation 2
    {
        float4 a = make_float4(0.f, 0.f, 0.f, 0.f);
        a = batch_sum(xh2, my2, c2 < 32 ? c2 : 32, lane, a);
        for (int base = 32; base < c2; base += 32) {          // cold path
            int mi = (base + lane < c2) ? b2[base + lane] : 0;
            a = batch_sum(xh2, mi, (c2 - base) < 32 ? (c2 - base) : 32, lane, a);
        }
        const float recip = 1.0f / (3.0f * (float)(cf2 > 0 ? cf2 : 1));
        acc.x += a.x * recip; acc.y += a.y * recip;
        acc.z += a.z * recip; acc.w += a.w * recip;
    }

    out[dst * (D / 4) + lane] = acc;
}

extern "C" void kernel_launch(void* const* d_in, const int* in_sizes, int n_in,
                              void* d_out, int out_size) {
    // metadata order: x_a, x_b, x_c, src_a, dst_a, src_b, dst_b, src_c, dst_c
    const float* xa = (const float*)d_in[0];
    const float* xb = (const float*)d_in[1];
    const float* xc = (const float*)d_in[2];
    const int* sa = (const int*)d_in[3];
    const int* da = (const int*)d_in[4];
    const int* sb = (const int*)d_in[5];
    const int* db = (const int*)d_in[6];
    const int* sc = (const int*)d_in[7];
    const int* dc = (const int*)d_in[8];
    float* out = (float*)d_out;

    zero_cursors<<<296, 256>>>();
    fill_convert_kernel<<<FILL_BLOCKS + CONV_BLOCKS, 256>>>(
        sa, da, sb, db, sc, dc,
        (const float4*)xa, (const float4*)xb, (const float4*)xc);

    // 100000 dsts * 32 threads = 3.2M threads; 8 warps/block -> 12500 blocks
    pull_kernel<<<12500, 256>>>((float4*)out);
}